// round 1
// baseline (speedup 1.0000x reference)
#include <cuda_runtime.h>
#include <cuda_bf16.h>
#include <math.h>

// Problem constants
#define BATCH 4
#define C     256
#define HEADS 4
#define DIM   64
#define NPIX  4096              // 64*64
#define GROUPS 8
#define CPG   32                // channels per group

// Scratch buffers (device globals: allocation-free)
__device__ float g_xn [BATCH * C * NPIX];          // normalized x   [b][c][n]
__device__ float g_qkv[BATCH * 3 * C * NPIX];      // qkv            [b][o][n], o = t*256 + h*64 + d
__device__ float g_ao [BATCH * C * NPIX];          // attention out  [b][h*64+d][n]

// ---------------------------------------------------------------------------
// GroupNorm: one block per (b, g). Fused stats + normalize.
// ---------------------------------------------------------------------------
__global__ void __launch_bounds__(256) groupnorm_kernel(
    const float* __restrict__ x, const float* __restrict__ gamma,
    const float* __restrict__ beta, float* __restrict__ xn)
{
    const int b = blockIdx.x >> 3;
    const int g = blockIdx.x & 7;
    const size_t off = ((size_t)b * C + (size_t)g * CPG) * NPIX;
    const float4* xp = (const float4*)(x + off);
    float4* xo = (float4*)(xn + off);
    const int tid = threadIdx.x;
    const int NV4 = CPG * NPIX / 4;   // 32768 float4

    float s = 0.f, ss = 0.f;
    for (int idx = tid; idx < NV4; idx += 256) {
        float4 v = xp[idx];
        s += (v.x + v.y) + (v.z + v.w);
        ss = fmaf(v.x, v.x, ss);
        ss = fmaf(v.y, v.y, ss);
        ss = fmaf(v.z, v.z, ss);
        ss = fmaf(v.w, v.w, ss);
    }
    // reduce across block
    __shared__ float rs[8], rss[8];
#pragma unroll
    for (int o = 16; o > 0; o >>= 1) {
        s  += __shfl_xor_sync(0xffffffffu, s,  o);
        ss += __shfl_xor_sync(0xffffffffu, ss, o);
    }
    if ((tid & 31) == 0) { rs[tid >> 5] = s; rss[tid >> 5] = ss; }
    __syncthreads();
    if (tid < 32) {
        float a  = (tid < 8) ? rs[tid]  : 0.f;
        float a2 = (tid < 8) ? rss[tid] : 0.f;
#pragma unroll
        for (int o = 4; o > 0; o >>= 1) {
            a  += __shfl_xor_sync(0xffffffffu, a,  o);
            a2 += __shfl_xor_sync(0xffffffffu, a2, o);
        }
        if (tid == 0) { rs[0] = a; rss[0] = a2; }
    }
    __syncthreads();
    const float inv_n = 1.0f / (float)(CPG * NPIX);
    const float mean = rs[0] * inv_n;
    const float var  = rss[0] * inv_n - mean * mean;
    const float rstd = rsqrtf(var + 1e-5f);

    for (int idx = tid; idx < NV4; idx += 256) {
        const int c = g * CPG + (idx >> 10);     // 1024 float4 per channel
        const float ga = gamma[c] * rstd;
        const float be = beta[c] - mean * ga;
        float4 v = xp[idx];
        v.x = fmaf(v.x, ga, be);
        v.y = fmaf(v.y, ga, be);
        v.z = fmaf(v.z, ga, be);
        v.w = fmaf(v.w, ga, be);
        xo[idx] = v;
    }
}

// ---------------------------------------------------------------------------
// Batched GEMM: C[bz] = A[M,K] * B[bz][K,N] + bias (+ residual)
// N = 4096 fixed. Tile 64x64x16, 256 threads, 4x4 micro-tile.
// ---------------------------------------------------------------------------
template<bool RES>
__global__ void __launch_bounds__(256) gemm_kernel(
    const float* __restrict__ A, const float* __restrict__ B,
    const float* __restrict__ bias, const float* __restrict__ R,
    float* __restrict__ Cout, int M, int K)
{
    const int N = NPIX;
    const int i0 = blockIdx.x * 64;
    const int m0 = blockIdx.y * 64;
    const int bz = blockIdx.z;
    const float* Bb = B + (size_t)bz * K * N;
    float* Cb = Cout + (size_t)bz * M * N;
    const float* Rb = R + (size_t)bz * M * N;

    __shared__ float As[16][68];
    __shared__ float Bs[16][68];

    const int tid = threadIdx.x;
    const int tx = tid & 15, ty = tid >> 4;

    const int am = tid >> 2;           // 0..63
    const int ak = (tid & 3) * 4;      // 0,4,8,12
    const int bk = tid >> 4;           // 0..15
    const int bi = (tid & 15) * 4;     // 0..60

    float acc[4][4] = {};

    for (int k0 = 0; k0 < K; k0 += 16) {
        float4 a4 = *(const float4*)&A [(size_t)(m0 + am) * K + k0 + ak];
        float4 b4 = *(const float4*)&Bb[(size_t)(k0 + bk) * N + i0 + bi];
        __syncthreads();
        As[ak + 0][am] = a4.x;
        As[ak + 1][am] = a4.y;
        As[ak + 2][am] = a4.z;
        As[ak + 3][am] = a4.w;
        *(float4*)&Bs[bk][bi] = b4;
        __syncthreads();
#pragma unroll
        for (int kk = 0; kk < 16; ++kk) {
            float4 av = *(const float4*)&As[kk][ty * 4];
            float4 bv = *(const float4*)&Bs[kk][tx * 4];
            acc[0][0] = fmaf(av.x, bv.x, acc[0][0]);
            acc[0][1] = fmaf(av.x, bv.y, acc[0][1]);
            acc[0][2] = fmaf(av.x, bv.z, acc[0][2]);
            acc[0][3] = fmaf(av.x, bv.w, acc[0][3]);
            acc[1][0] = fmaf(av.y, bv.x, acc[1][0]);
            acc[1][1] = fmaf(av.y, bv.y, acc[1][1]);
            acc[1][2] = fmaf(av.y, bv.z, acc[1][2]);
            acc[1][3] = fmaf(av.y, bv.w, acc[1][3]);
            acc[2][0] = fmaf(av.z, bv.x, acc[2][0]);
            acc[2][1] = fmaf(av.z, bv.y, acc[2][1]);
            acc[2][2] = fmaf(av.z, bv.z, acc[2][2]);
            acc[2][3] = fmaf(av.z, bv.w, acc[2][3]);
            acc[3][0] = fmaf(av.w, bv.x, acc[3][0]);
            acc[3][1] = fmaf(av.w, bv.y, acc[3][1]);
            acc[3][2] = fmaf(av.w, bv.z, acc[3][2]);
            acc[3][3] = fmaf(av.w, bv.w, acc[3][3]);
        }
    }

#pragma unroll
    for (int r = 0; r < 4; ++r) {
        const int mm = m0 + ty * 4 + r;
        const float bs = bias[mm];
        const size_t idx = (size_t)mm * N + i0 + tx * 4;
        float4 o4;
        o4.x = acc[r][0] + bs;
        o4.y = acc[r][1] + bs;
        o4.z = acc[r][2] + bs;
        o4.w = acc[r][3] + bs;
        if (RES) {
            float4 r4 = *(const float4*)&Rb[idx];
            o4.x += r4.x; o4.y += r4.y; o4.z += r4.z; o4.w += r4.w;
        }
        *(float4*)&Cb[idx] = o4;
    }
}

// ---------------------------------------------------------------------------
// Flash attention: one thread per query row. Bq = Bk = 64, D = 64.
// grid: (N/64, H, B), block: 64 threads.
// ---------------------------------------------------------------------------
__global__ void __launch_bounds__(64) attn_kernel(
    const float* __restrict__ qkv, float* __restrict__ ao)
{
    const int i0 = blockIdx.x * 64;
    const int h  = blockIdx.y;
    const int b  = blockIdx.z;
    const int tid = threadIdx.x;

    const size_t base = (size_t)b * (3 * C * NPIX) + (size_t)h * DIM * NPIX;
    const float* qp = qkv + base;
    const float* kp = qkv + base + (size_t)C * NPIX;
    const float* vp = qkv + base + (size_t)(2 * C) * NPIX;

    __shared__ float Ks[64][68];
    __shared__ float Vs[64][68];
    __shared__ float Ps[64][17];

    float q[DIM];
#pragma unroll
    for (int d = 0; d < DIM; ++d)
        q[d] = qp[(size_t)d * NPIX + i0 + tid] * 0.125f;   // dim^-0.5

    float acc[DIM];
#pragma unroll
    for (int d = 0; d < DIM; ++d) acc[d] = 0.f;
    float m = -3.0e38f, l = 0.f;

    for (int j0 = 0; j0 < NPIX; j0 += 64) {
        __syncthreads();
#pragma unroll
        for (int d = 0; d < DIM; ++d) {
            Ks[tid][d] = kp[(size_t)d * NPIX + j0 + tid];
            Vs[tid][d] = vp[(size_t)d * NPIX + j0 + tid];
        }
        __syncthreads();

        for (int c0 = 0; c0 < 64; c0 += 16) {
            float s[16];
#pragma unroll
            for (int jj = 0; jj < 16; ++jj) {
                float s0 = 0.f, s1 = 0.f, s2 = 0.f, s3 = 0.f;
#pragma unroll
                for (int d4 = 0; d4 < 16; ++d4) {
                    float4 k4 = *(const float4*)&Ks[c0 + jj][d4 * 4];
                    s0 = fmaf(q[4 * d4 + 0], k4.x, s0);
                    s1 = fmaf(q[4 * d4 + 1], k4.y, s1);
                    s2 = fmaf(q[4 * d4 + 2], k4.z, s2);
                    s3 = fmaf(q[4 * d4 + 3], k4.w, s3);
                }
                s[jj] = (s0 + s1) + (s2 + s3);
            }

            // online softmax update
            float mc = s[0];
#pragma unroll
            for (int jj = 1; jj < 16; ++jj) mc = fmaxf(mc, s[jj]);
            const float mnew = fmaxf(m, mc);
            const float corr = __expf(m - mnew);
            l *= corr;
#pragma unroll
            for (int jj = 0; jj < 16; ++jj) {
                const float p = __expf(s[jj] - mnew);
                l += p;
                Ps[tid][jj] = p;      // thread-private row, no sync needed
            }
            m = mnew;
#pragma unroll
            for (int d = 0; d < DIM; ++d) acc[d] *= corr;

            // PV: jj rolled (p via smem), d4 unrolled (acc stays in regs)
            for (int jj = 0; jj < 16; ++jj) {
                const float p = Ps[tid][jj];
                const float* vr = &Vs[c0 + jj][0];
#pragma unroll
                for (int d4 = 0; d4 < 16; ++d4) {
                    float4 v4 = *(const float4*)&vr[d4 * 4];
                    acc[4 * d4 + 0] = fmaf(p, v4.x, acc[4 * d4 + 0]);
                    acc[4 * d4 + 1] = fmaf(p, v4.y, acc[4 * d4 + 1]);
                    acc[4 * d4 + 2] = fmaf(p, v4.z, acc[4 * d4 + 2]);
                    acc[4 * d4 + 3] = fmaf(p, v4.w, acc[4 * d4 + 3]);
                }
            }
        }
    }

    const float inv_l = 1.0f / l;
    float* op = ao + (size_t)b * (C * NPIX) + (size_t)h * DIM * NPIX + i0 + tid;
#pragma unroll
    for (int d = 0; d < DIM; ++d)
        op[(size_t)d * NPIX] = acc[d] * inv_l;
}

// ---------------------------------------------------------------------------
// Launch
// ---------------------------------------------------------------------------
extern "C" void kernel_launch(void* const* d_in, const int* in_sizes, int n_in,
                              void* d_out, int out_size)
{
    const float* x      = (const float*)d_in[0];
    const float* gamma  = (const float*)d_in[1];
    const float* beta   = (const float*)d_in[2];
    const float* w_qkv  = (const float*)d_in[3];
    const float* b_qkv  = (const float*)d_in[4];
    const float* w_proj = (const float*)d_in[5];
    const float* b_proj = (const float*)d_in[6];
    float* out = (float*)d_out;

    float *xn, *qkv, *ao;
    cudaGetSymbolAddress((void**)&xn,  g_xn);
    cudaGetSymbolAddress((void**)&qkv, g_qkv);
    cudaGetSymbolAddress((void**)&ao,  g_ao);

    // 1) GroupNorm
    groupnorm_kernel<<<BATCH * GROUPS, 256>>>(x, gamma, beta, xn);

    // 2) QKV projection: [768,256] x [256,4096] per batch
    {
        dim3 grid(NPIX / 64, (3 * C) / 64, BATCH);
        gemm_kernel<false><<<grid, 256>>>(w_qkv, xn, b_qkv, nullptr, qkv, 3 * C, C);
    }

    // 3) Attention
    {
        dim3 grid(NPIX / 64, HEADS, BATCH);
        attn_kernel<<<grid, 64>>>(qkv, ao);
    }

    // 4) Output projection + bias + residual
    {
        dim3 grid(NPIX / 64, C / 64, BATCH);
        gemm_kernel<true><<<grid, 256>>>(w_proj, ao, b_proj, x, out, C, C);
    }
}